// round 5
// baseline (speedup 1.0000x reference)
#include <cuda_runtime.h>

// ts_cov: sliding-window pairwise covariance.
// x: [B=256, T=512, F=32] f32 -> out: [B, S=508, C=496] f32
// cov[b,s,c(i,j)] = mean5(x_i x_j) - mean5(x_i)*mean5(x_j)
//
// Thread t owns adjacent pairs c=2t, 2t+1, advanced together with packed
// f32x2 math. smem holds duplicated pairs sxp[r][f] = (x_f, x_{f+1}) so the
// packed y operand is ONE LDS.64. The 16 "boundary" couples (where 2t+1
// starts a new i-row) get a garbage hi lane in the fast path; a post-barrier
// scalar fixup recomputes those 16 pairs and overwrites (WAW via barrier).

#define B_DIM 256
#define T_DIM 512
#define F_DIM 32
#define W 5
#define S_DIM (T_DIM - W + 1)            // 508
#define C_DIM (F_DIM * (F_DIM - 1) / 2)  // 496
#define HALF_C (C_DIM / 2)               // 248
#define S_TILE 32
#define ROWS (S_TILE + W - 1)            // 36
#define NTHREADS 256
#define TILES_PER_B ((S_DIM + S_TILE - 1) / S_TILE) // 16

typedef unsigned long long u64;

__device__ __forceinline__ u64 pack2(float lo, float hi) {
    u64 r;
    asm("mov.b64 %0, {%1, %2};" : "=l"(r) : "r"(__float_as_uint(lo)), "r"(__float_as_uint(hi)));
    return r;
}
__device__ __forceinline__ u64 mul2(u64 a, u64 b) {
    u64 r; asm("mul.rn.f32x2 %0, %1, %2;" : "=l"(r) : "l"(a), "l"(b)); return r;
}
__device__ __forceinline__ u64 add2(u64 a, u64 b) {
    u64 r; asm("add.rn.f32x2 %0, %1, %2;" : "=l"(r) : "l"(a), "l"(b)); return r;
}
__device__ __forceinline__ u64 sub2(u64 a, u64 b) {
    u64 r; asm("sub.rn.f32x2 %0, %1, %2;" : "=l"(r) : "l"(a), "l"(b)); return r;
}
__device__ __forceinline__ u64 fma2(u64 a, u64 b, u64 c) {
    u64 r; asm("fma.rn.f32x2 %0, %1, %2, %3;" : "=l"(r) : "l"(a), "l"(b), "l"(c)); return r;
}

// closed-form pair decode c -> (i, j), triu_indices(F, k=1) order
__device__ __forceinline__ void decode_pair(int c, int& io, int& jo) {
    const int TF = 2 * F_DIM - 1; // 63
    float disc = (float)(TF * TF - 8 * c);
    int i = (int)(((float)TF - sqrtf(disc)) * 0.5f);
    int off = (i * (TF - i)) >> 1;
    if (c < off)                          { --i; off = (i * (TF - i)) >> 1; }
    else if (c >= off + (F_DIM - 1 - i))  { ++i; off = (i * (TF - i)) >> 1; }
    io = i; jo = c - off + i + 1;
}

__global__ __launch_bounds__(NTHREADS, 5)
void ts_cov_kernel(const float* __restrict__ x, float* __restrict__ out) {
    __shared__ float2 sxp[ROWS][F_DIM];  // (x_f, x_{f+1}); f=31 -> (x_31, x_31)

    const int b     = blockIdx.y;
    const int s0    = blockIdx.x * S_TILE;
    const int s_cnt = min(S_TILE, S_DIM - s0);   // 32, or 28 on last tile
    const int rows  = s_cnt + W - 1;
    const int tid   = threadIdx.x;

    // ---- Stage x rows into duplicated-pair smem ----
    const float* gx = x + ((long)b * T_DIM + s0) * F_DIM;
    for (int idx = tid; idx < rows * F_DIM; idx += NTHREADS) {
        const int r = idx >> 5;
        const int f = idx & 31;
        const float v = gx[idx];
        sxp[r][f].x = v;
        if (f > 0)  sxp[r][f - 1].y = v;
        if (f == 31) sxp[r][31].y = v;   // pad hi lane
    }
    __syncthreads();

    float* const obase = out + ((long)b * S_DIM + s0) * C_DIM;
    const u64 INVP = pack2(0.2f, 0.2f);     //  1/W
    const u64 NI25 = pack2(-0.04f, -0.04f); // -1/W^2

    if (tid < HALF_C) {
        int iA, jA;
        decode_pair(2 * tid, iA, jA);
        // fast path assumes pair hi = (iA, jA+1); boundary couples get
        // garbage in the hi lane, fixed up after the barrier.

        u64 xr[W], yr[W];
        u64 s2x = 0ull, s2y = 0ull, s2p = 0ull;
        #pragma unroll
        for (int t = 0; t < W; ++t) {
            const float a = sxp[t][iA].x;
            const u64 x2 = pack2(a, a);
            const u64 y2 = *reinterpret_cast<const u64*>(&sxp[t][jA]);
            const u64 p2 = mul2(x2, y2);
            xr[t] = x2; yr[t] = y2;
            s2x = add2(s2x, x2); s2y = add2(s2y, y2); s2p = add2(s2p, p2);
        }

        float2* o = (float2*)(obase + 2 * tid);   // 8B-aligned (even c)

        if (s_cnt == S_TILE) {
            #pragma unroll
            for (int sl = 0; sl < S_TILE; ++sl) {
                const u64 cov2 = fma2(mul2(s2x, s2y), NI25, mul2(s2p, INVP));
                float2 cv; cv.x = __uint_as_float((unsigned)cov2);
                cv.y = __uint_as_float((unsigned)(cov2 >> 32));
                __stcs((float2*)((float*)o + (long)sl * C_DIM), cv);
                if (sl + 1 < S_TILE) {
                    const int r = sl + W, k = sl % W;
                    const float a = sxp[r][iA].x;
                    const u64 x2 = pack2(a, a);
                    const u64 y2 = *reinterpret_cast<const u64*>(&sxp[r][jA]);
                    const u64 po = mul2(xr[k], yr[k]);
                    const u64 p2 = mul2(x2, y2);
                    s2p = add2(s2p, sub2(p2, po));
                    s2x = add2(s2x, sub2(x2, xr[k]));
                    s2y = add2(s2y, sub2(y2, yr[k]));
                    xr[k] = x2; yr[k] = y2;
                }
            }
        } else {
            #pragma unroll
            for (int sl = 0; sl < S_TILE; ++sl) {
                if (sl < s_cnt) {
                    const u64 cov2 = fma2(mul2(s2x, s2y), NI25, mul2(s2p, INVP));
                    float2 cv; cv.x = __uint_as_float((unsigned)cov2);
                    cv.y = __uint_as_float((unsigned)(cov2 >> 32));
                    __stcs((float2*)((float*)o + (long)sl * C_DIM), cv);
                }
                if (sl + 1 < s_cnt) {
                    const int r = sl + W, k = sl % W;
                    const float a = sxp[r][iA].x;
                    const u64 x2 = pack2(a, a);
                    const u64 y2 = *reinterpret_cast<const u64*>(&sxp[r][jA]);
                    const u64 po = mul2(xr[k], yr[k]);
                    const u64 p2 = mul2(x2, y2);
                    s2p = add2(s2p, sub2(p2, po));
                    s2x = add2(s2x, sub2(x2, xr[k]));
                    s2y = add2(s2y, sub2(y2, yr[k]));
                    xr[k] = x2; yr[k] = y2;
                }
            }
        }
    }

    // ---- Boundary fixup: 16 pairs whose row starts at an odd c ----
    // Barrier orders the fast-path STG.64 (garbage hi) before the overwrite.
    __syncthreads();

    if (tid < 16) {
        // boundary rows i in {1,2,5,6,9,10,...,29,30}; pair (i, i+1), c = start(i)
        const int i = 4 * (tid >> 1) + (tid & 1) + 1;
        const int c = (i * (63 - i)) >> 1;   // odd row start
        // pair values (x_i, x_{i+1}) come packed from sxp[r][i]
        float si = 0.f, sj = 0.f, sp = 0.f;
        #pragma unroll
        for (int t = 0; t < W; ++t) {
            const float2 v = sxp[t][i];
            si += v.x; sj += v.y; sp += v.x * v.y;
        }
        for (int sl = 0; sl < s_cnt; ++sl) {
            const float cov = fmaf(sp, 0.2f, -(si * sj) * 0.04f);
            __stcs(obase + (long)sl * C_DIM + c, cov);
            if (sl + 1 < s_cnt) {
                const float2 vn = sxp[sl + W][i];
                const float2 vo = sxp[sl][i];
                sp += vn.x * vn.y - vo.x * vo.y;
                si += vn.x - vo.x;
                sj += vn.y - vo.y;
            }
        }
    }
}

extern "C" void kernel_launch(void* const* d_in, const int* in_sizes, int n_in,
                              void* d_out, int out_size) {
    const float* x = (const float*)d_in[0];
    float* out = (float*)d_out;
    (void)in_sizes; (void)n_in; (void)out_size;
    dim3 grid(TILES_PER_B, B_DIM);
    ts_cov_kernel<<<grid, NTHREADS>>>(x, out);
}

// round 7
// speedup vs baseline: 1.0602x; 1.0602x over previous
#include <cuda_runtime.h>

// ts_cov: sliding-window pairwise covariance.
// x: [B=256, T=512, F=32] f32 -> out: [B, S=508, C=496] f32
// cov[b,s,c(i,j)] = mean5(x_i x_j) - mean5(x_i)*mean5(x_j)
//
// Thread t owns ADJACENT pairs c = 2t, 2t+1 (independently decoded — no
// boundary special cases), advanced together with packed f32x2 arithmetic.
// Output written as one STG.64 per window (register-pair store, no unpack).

#define B_DIM 256
#define T_DIM 512
#define F_DIM 32
#define W 5
#define S_DIM (T_DIM - W + 1)            // 508
#define C_DIM (F_DIM * (F_DIM - 1) / 2)  // 496
#define HALF_C (C_DIM / 2)               // 248
#define S_TILE 32
#define ROWS (S_TILE + W - 1)            // 36
#define NTHREADS 256
#define TILES_PER_B ((S_DIM + S_TILE - 1) / S_TILE) // 16

typedef unsigned long long u64;

__device__ __forceinline__ u64 pack2(float lo, float hi) {
    u64 r;
    asm("mov.b64 %0, {%1, %2};" : "=l"(r) : "r"(__float_as_uint(lo)), "r"(__float_as_uint(hi)));
    return r;
}
__device__ __forceinline__ float2 as_f2(u64 v) {
    float2 f;
    unsigned a, b;
    asm("mov.b64 {%0, %1}, %2;" : "=r"(a), "=r"(b) : "l"(v));
    f.x = __uint_as_float(a); f.y = __uint_as_float(b);
    return f;
}
__device__ __forceinline__ u64 mul2(u64 a, u64 b) {
    u64 r; asm("mul.rn.f32x2 %0, %1, %2;" : "=l"(r) : "l"(a), "l"(b)); return r;
}
__device__ __forceinline__ u64 add2(u64 a, u64 b) {
    u64 r; asm("add.rn.f32x2 %0, %1, %2;" : "=l"(r) : "l"(a), "l"(b)); return r;
}
__device__ __forceinline__ u64 sub2(u64 a, u64 b) {
    u64 r; asm("sub.rn.f32x2 %0, %1, %2;" : "=l"(r) : "l"(a), "l"(b)); return r;
}
__device__ __forceinline__ u64 fma2(u64 a, u64 b, u64 c) {
    u64 r; asm("fma.rn.f32x2 %0, %1, %2, %3;" : "=l"(r) : "l"(a), "l"(b), "l"(c)); return r;
}

// closed-form pair decode c -> (i, j), triu_indices(F, k=1) order
__device__ __forceinline__ void decode_pair(int c, int& io, int& jo) {
    const int TF = 2 * F_DIM - 1; // 63
    float disc = (float)(TF * TF - 8 * c);
    int i = (int)(((float)TF - sqrtf(disc)) * 0.5f);
    int off = (i * (TF - i)) >> 1;
    if (c < off)                          { --i; off = (i * (TF - i)) >> 1; }
    else if (c >= off + (F_DIM - 1 - i))  { ++i; off = (i * (TF - i)) >> 1; }
    io = i; jo = c - off + i + 1;
}

__global__ __launch_bounds__(NTHREADS, 5)
void ts_cov_kernel(const float* __restrict__ x, float* __restrict__ out) {
    __shared__ float sx[ROWS][F_DIM];

    const int b     = blockIdx.y;
    const int s0    = blockIdx.x * S_TILE;
    const int s_cnt = min(S_TILE, S_DIM - s0);   // 32, or 28 on last tile
    const int rows  = s_cnt + W - 1;
    const int tid   = threadIdx.x;

    // ---- Stage x[b, s0 : s0+rows, :] into smem (float4, coalesced) ----
    const float4* gx = (const float4*)(x + ((long)b * T_DIM + s0) * F_DIM);
    const int nv = rows * (F_DIM / 4);
    for (int idx = tid; idx < nv; idx += NTHREADS)
        ((float4*)sx)[idx] = gx[idx];
    __syncthreads();

    if (tid >= HALF_C) return;

    int iA, jA, iB, jB;
    decode_pair(2 * tid,     iA, jA);
    decode_pair(2 * tid + 1, iB, jB);

    const u64 INVP = pack2(0.2f, 0.2f);     //  1/W
    const u64 NI25 = pack2(-0.04f, -0.04f); // -1/W^2

    // ---- Init sliding rings (values; exit products recomputed, bit-identical) ----
    u64 xr[W], yr[W];
    u64 s2x = 0ull, s2y = 0ull, s2p = 0ull;
    #pragma unroll
    for (int t = 0; t < W; ++t) {
        const u64 x2 = pack2(sx[t][iA], sx[t][iB]);
        const u64 y2 = pack2(sx[t][jA], sx[t][jB]);
        const u64 p2 = mul2(x2, y2);
        xr[t] = x2; yr[t] = y2;
        s2x = add2(s2x, x2); s2y = add2(s2y, y2); s2p = add2(s2p, p2);
    }

    // even element offset -> 8B-aligned float2 stores
    float* o = out + ((long)b * S_DIM + s0) * C_DIM + 2 * tid;

    if (s_cnt == S_TILE) {
        #pragma unroll
        for (int sl = 0; sl < S_TILE; ++sl) {
            const u64 cov2 = fma2(mul2(s2x, s2y), NI25, mul2(s2p, INVP));
            *(float2*)(o + (long)sl * C_DIM) = as_f2(cov2);
            if (sl + 1 < S_TILE) {
                const int r = sl + W, k = sl % W;
                const u64 x2 = pack2(sx[r][iA], sx[r][iB]);
                const u64 y2 = pack2(sx[r][jA], sx[r][jB]);
                const u64 po = mul2(xr[k], yr[k]);
                const u64 p2 = mul2(x2, y2);
                s2p = add2(s2p, sub2(p2, po));
                s2x = add2(s2x, sub2(x2, xr[k]));
                s2y = add2(s2y, sub2(y2, yr[k]));
                xr[k] = x2; yr[k] = y2;
            }
        }
    } else {
        #pragma unroll
        for (int sl = 0; sl < S_TILE; ++sl) {
            if (sl < s_cnt) {
                const u64 cov2 = fma2(mul2(s2x, s2y), NI25, mul2(s2p, INVP));
                *(float2*)(o + (long)sl * C_DIM) = as_f2(cov2);
            }
            if (sl + 1 < s_cnt) {
                const int r = sl + W, k = sl % W;
                const u64 x2 = pack2(sx[r][iA], sx[r][iB]);
                const u64 y2 = pack2(sx[r][jA], sx[r][jB]);
                const u64 po = mul2(xr[k], yr[k]);
                const u64 p2 = mul2(x2, y2);
                s2p = add2(s2p, sub2(p2, po));
                s2x = add2(s2x, sub2(x2, xr[k]));
                s2y = add2(s2y, sub2(y2, yr[k]));
                xr[k] = x2; yr[k] = y2;
            }
        }
    }
}

extern "C" void kernel_launch(void* const* d_in, const int* in_sizes, int n_in,
                              void* d_out, int out_size) {
    const float* x = (const float*)d_in[0];
    float* out = (float*)d_out;
    (void)in_sizes; (void)n_in; (void)out_size;
    dim3 grid(TILES_PER_B, B_DIM);
    ts_cov_kernel<<<grid, NTHREADS>>>(x, out);
}

// round 9
// speedup vs baseline: 1.1903x; 1.1228x over previous
#include <cuda_runtime.h>

// ts_cov: sliding-window pairwise covariance.
// x: [B=256, T=512, F=32] f32 -> out: [B, S=508, C=496] f32
// cov[b,s,c(i,j)] = mean5(x_i x_j) - mean5(x_i)*mean5(x_j)
//
// Thread t owns ADJACENT pairs c = 2t, 2t+1, advanced together with packed
// f32x2 arithmetic; one STG.64 (evict-first) per window. S_TILE=64 windows
// per block amortizes decode/ring-init/staging; tail tile (60) is a separate
// full-unroll template instantiation (no per-iteration predicates).

#define B_DIM 256
#define T_DIM 512
#define F_DIM 32
#define W 5
#define S_DIM (T_DIM - W + 1)            // 508
#define C_DIM (F_DIM * (F_DIM - 1) / 2)  // 496
#define HALF_C (C_DIM / 2)               // 248
#define S_TILE 64
#define ROWS (S_TILE + W - 1)            // 68
#define NTHREADS 256
#define TILES_PER_B ((S_DIM + S_TILE - 1) / S_TILE) // 8
#define TAIL_CNT (S_DIM - (TILES_PER_B - 1) * S_TILE) // 60

typedef unsigned long long u64;

__device__ __forceinline__ u64 pack2(float lo, float hi) {
    u64 r;
    asm("mov.b64 %0, {%1, %2};" : "=l"(r) : "r"(__float_as_uint(lo)), "r"(__float_as_uint(hi)));
    return r;
}
__device__ __forceinline__ float2 as_f2(u64 v) {
    float2 f;
    unsigned a, b;
    asm("mov.b64 {%0, %1}, %2;" : "=r"(a), "=r"(b) : "l"(v));
    f.x = __uint_as_float(a); f.y = __uint_as_float(b);
    return f;
}
__device__ __forceinline__ u64 mul2(u64 a, u64 b) {
    u64 r; asm("mul.rn.f32x2 %0, %1, %2;" : "=l"(r) : "l"(a), "l"(b)); return r;
}
__device__ __forceinline__ u64 add2(u64 a, u64 b) {
    u64 r; asm("add.rn.f32x2 %0, %1, %2;" : "=l"(r) : "l"(a), "l"(b)); return r;
}
__device__ __forceinline__ u64 sub2(u64 a, u64 b) {
    u64 r; asm("sub.rn.f32x2 %0, %1, %2;" : "=l"(r) : "l"(a), "l"(b)); return r;
}
__device__ __forceinline__ u64 fma2(u64 a, u64 b, u64 c) {
    u64 r; asm("fma.rn.f32x2 %0, %1, %2, %3;" : "=l"(r) : "l"(a), "l"(b), "l"(c)); return r;
}

// closed-form pair decode c -> (i, j), triu_indices(F, k=1) order
__device__ __forceinline__ void decode_pair(int c, int& io, int& jo) {
    const int TF = 2 * F_DIM - 1; // 63
    float disc = (float)(TF * TF - 8 * c);
    int i = (int)(((float)TF - sqrtf(disc)) * 0.5f);
    int off = (i * (TF - i)) >> 1;
    if (c < off)                          { --i; off = (i * (TF - i)) >> 1; }
    else if (c >= off + (F_DIM - 1 - i))  { ++i; off = (i * (TF - i)) >> 1; }
    io = i; jo = c - off + i + 1;
}

template <int SCNT>
__device__ __forceinline__ void cov_tile(const float (*sx)[F_DIM], float* o,
                                         int iA, int jA, int iB, int jB) {
    const u64 INVP = pack2(0.2f, 0.2f);     //  1/W
    const u64 NI25 = pack2(-0.04f, -0.04f); // -1/W^2

    // Init sliding rings (values; exit products recomputed, bit-identical)
    u64 xr[W], yr[W];
    u64 s2x = 0ull, s2y = 0ull, s2p = 0ull;
    #pragma unroll
    for (int t = 0; t < W; ++t) {
        const u64 x2 = pack2(sx[t][iA], sx[t][iB]);
        const u64 y2 = pack2(sx[t][jA], sx[t][jB]);
        const u64 p2 = mul2(x2, y2);
        xr[t] = x2; yr[t] = y2;
        s2x = add2(s2x, x2); s2y = add2(s2y, y2); s2p = add2(s2p, p2);
    }

    #pragma unroll
    for (int sl = 0; sl < SCNT; ++sl) {
        const u64 cov2 = fma2(mul2(s2x, s2y), NI25, mul2(s2p, INVP));
        __stcs((float2*)(o + (long)sl * C_DIM), as_f2(cov2));
        if (sl + 1 < SCNT) {
            const int r = sl + W, k = sl % W;
            const u64 x2 = pack2(sx[r][iA], sx[r][iB]);
            const u64 y2 = pack2(sx[r][jA], sx[r][jB]);
            const u64 po = mul2(xr[k], yr[k]);
            const u64 p2 = mul2(x2, y2);
            s2p = add2(s2p, sub2(p2, po));
            s2x = add2(s2x, sub2(x2, xr[k]));
            s2y = add2(s2y, sub2(y2, yr[k]));
            xr[k] = x2; yr[k] = y2;
        }
    }
}

__global__ __launch_bounds__(NTHREADS, 5)
void ts_cov_kernel(const float* __restrict__ x, float* __restrict__ out) {
    __shared__ float sx[ROWS][F_DIM];

    const int b     = blockIdx.y;
    const int s0    = blockIdx.x * S_TILE;
    const bool full = (s0 + S_TILE <= S_DIM);
    const int rows  = (full ? S_TILE : TAIL_CNT) + W - 1;
    const int tid   = threadIdx.x;

    // ---- Stage x[b, s0 : s0+rows, :] into smem (float4, coalesced) ----
    const float4* gx = (const float4*)(x + ((long)b * T_DIM + s0) * F_DIM);
    const int nv = rows * (F_DIM / 4);
    for (int idx = tid; idx < nv; idx += NTHREADS)
        ((float4*)sx)[idx] = gx[idx];
    __syncthreads();

    if (tid >= HALF_C) return;

    int iA, jA, iB, jB;
    decode_pair(2 * tid,     iA, jA);
    decode_pair(2 * tid + 1, iB, jB);

    // even element offset -> 8B-aligned float2 stores
    float* o = out + ((long)b * S_DIM + s0) * C_DIM + 2 * tid;

    if (full) cov_tile<S_TILE>(sx, o, iA, jA, iB, jB);
    else      cov_tile<TAIL_CNT>(sx, o, iA, jA, iB, jB);
}

extern "C" void kernel_launch(void* const* d_in, const int* in_sizes, int n_in,
                              void* d_out, int out_size) {
    const float* x = (const float*)d_in[0];
    float* out = (float*)d_out;
    (void)in_sizes; (void)n_in; (void)out_size;
    dim3 grid(TILES_PER_B, B_DIM);
    ts_cov_kernel<<<grid, NTHREADS>>>(x, out);
}